// round 13
// baseline (speedup 1.0000x reference)
#include <cuda_runtime.h>
#include <cooperative_groups.h>
namespace cg = cooperative_groups;

#define Nn 20000
#define Ee 160000

// ---------------- scratch (device globals: allocation-free) ----------------
__device__ float g_h[Nn * 256];      // per node: [u][ h0, h1x, h1y, h1z ] interleaved
__device__ float g_sc[Nn * 320];     // [sc0(128) | sc1 as w*3+d (192)]
__device__ int   g_cnt[Nn];
__device__ int   g_cur[Nn];
__device__ int   g_off[Nn + 1];
__device__ int   g_bsum[256];
__device__ int   g_esrc[Ee];         // src*64 (float4 row index into g_h) per dst-sorted edge
__device__ float g_hid[Ee * 8];      // silu(emb@Wm1) per dst-sorted edge
__device__ float g_eap[Ee * 4];      // edge_attrs per dst-sorted edge

__device__ __forceinline__ float silu_f(float x) { return x / (1.0f + __expf(-x)); }

extern __shared__ float smem_dyn[];

// ---------------- CSR build + fused edge prep: cooperative, parallel scan ----------
#define CSR_BLOCKS 148
#define CSR_CHUNK  ((Nn + CSR_BLOCKS - 1) / CSR_BLOCKS)   // 136

__global__ void k_csr(const int* __restrict__ ei, const float* __restrict__ emb,
                      const float* __restrict__ ea, const float* __restrict__ Wm1) {
    cg::grid_group grid = cg::this_grid();
    __shared__ float wm1[64];
    __shared__ int sh[512];
    int t = threadIdx.x;
    int tid = blockIdx.x * blockDim.x + t;
    int nthr = gridDim.x * blockDim.x;
    if (t < 64) wm1[t] = Wm1[t];
    __syncthreads();

    // phase 0: zero
    for (int i = tid; i < Nn; i += nthr) { g_cnt[i] = 0; g_cur[i] = 0; }
    grid.sync();

    // phase 1: histogram
    for (int e = tid; e < Ee; e += nthr) atomicAdd(&g_cnt[ei[Ee + e]], 1);
    grid.sync();

    // phase 2a: per-block scan of its chunk (local exclusive), record block total
    int base = blockIdx.x * CSR_CHUNK;
    {
        int v = (t < CSR_CHUNK && base + t < Nn) ? g_cnt[base + t] : 0;
        sh[t] = v;
        __syncthreads();
        for (int off = 1; off < 512; off <<= 1) {
            int x = (t >= off) ? sh[t - off] : 0;
            __syncthreads();
            sh[t] += x;
            __syncthreads();
        }
        if (t < CSR_CHUNK && base + t < Nn) g_off[base + t] = sh[t] - v;  // local excl
        if (t == 511) g_bsum[blockIdx.x] = sh[511];
        __syncthreads();
    }
    grid.sync();

    // phase 2b: block 0 scans the block totals
    if (blockIdx.x == 0) {
        int v = (t < CSR_BLOCKS) ? g_bsum[t] : 0;
        sh[t] = v;
        __syncthreads();
        for (int off = 1; off < 512; off <<= 1) {
            int x = (t >= off) ? sh[t - off] : 0;
            __syncthreads();
            sh[t] += x;
            __syncthreads();
        }
        if (t < CSR_BLOCKS) g_bsum[t] = sh[t] - v;  // exclusive
        if (t == CSR_BLOCKS - 1) g_off[Nn] = sh[t]; // grand total = Ee
    }
    grid.sync();

    // phase 2c: add block prefix
    {
        int pre = g_bsum[blockIdx.x];
        if (t < CSR_CHUNK && base + t < Nn) g_off[base + t] += pre;
    }
    grid.sync();

    // phase 3: scatter + edge prep fused (reads sequential in e, writes scattered)
    const float inv_e = 0.35355339059327373f;   // 1/sqrt(8)
    for (int e = tid; e < Ee; e += nthr) {
        int src = ei[e];
        int dst = ei[Ee + e];
        int pos = g_off[dst] + atomicAdd(&g_cur[dst], 1);
        g_esrc[pos] = src * 64;     // pre-scaled float4-row index
        float4 e0 = *(const float4*)(emb + (size_t)e * 8);
        float4 e1 = *(const float4*)(emb + (size_t)e * 8 + 4);
        float h[8];
        #pragma unroll
        for (int j = 0; j < 8; j++) {
            float a = e0.x * wm1[0 * 8 + j] + e0.y * wm1[1 * 8 + j]
                    + e0.z * wm1[2 * 8 + j] + e0.w * wm1[3 * 8 + j]
                    + e1.x * wm1[4 * 8 + j] + e1.y * wm1[5 * 8 + j]
                    + e1.z * wm1[6 * 8 + j] + e1.w * wm1[7 * 8 + j];
            h[j] = silu_f(a * inv_e);
        }
        *(float4*)(g_hid + (size_t)pos * 8)     = make_float4(h[0], h[1], h[2], h[3]);
        *(float4*)(g_hid + (size_t)pos * 8 + 4) = make_float4(h[4], h[5], h[6], h[7]);
        *(float4*)(g_eap + (size_t)pos * 4) = *(const float4*)(ea + (size_t)e * 4);
    }
}

// ---------------- h = lin1(node_feats), interleaved output layout ----------------
__global__ void k_h(const float* __restrict__ nf,
                    const float* __restrict__ W10, const float* __restrict__ W11) {
    __shared__ float w10[4096], w11[4096], xs[256], os[256];
    int t = threadIdx.x;
    for (int i = t; i < 4096; i += 256) { w10[i] = W10[i]; w11[i] = W11[i]; }
    __syncthreads();
    for (int n = blockIdx.x; n < Nn; n += gridDim.x) {
        xs[t] = nf[(size_t)n * 256 + t];
        __syncthreads();
        float acc = 0.f;
        if (t < 64) {
            #pragma unroll 8
            for (int k = 0; k < 64; k++) acc += xs[k] * w10[k * 64 + t];
            os[t * 4] = acc * 0.125f;
        } else {
            int i = t - 64, d = i >> 6, v = i & 63;
            #pragma unroll 8
            for (int k = 0; k < 64; k++) acc += xs[64 + k * 3 + d] * w11[k * 64 + v];
            os[v * 4 + 1 + d] = acc * 0.125f;
        }
        __syncthreads();
        g_h[(size_t)n * 256 + t] = os[t];
        __syncthreads();
    }
}

// ---------------- sc (skip connection): 512 thr, 16 warps/SM, warp x 2 nodes ----------
// round-5 proven config (96us)
__global__ __launch_bounds__(512, 1)
void k_sc(const float* __restrict__ nf, const float* __restrict__ na,
          const float* __restrict__ Wsc0, const float* __restrict__ Wsc1) {
    float* wsc0 = smem_dyn;            // 32768 floats (128KB)
    float* wsc1 = wsc0 + 32768;        // 16384 floats (64KB)
    float* xsb  = wsc1 + 16384;        // 16 warps * 2 nodes * 256 floats (32KB)
    int t = threadIdx.x;               // 512 threads
    for (int i = t; i < 32768; i += 512) wsc0[i] = Wsc0[i];
    for (int i = t; i < 16384; i += 512) wsc1[i] = Wsc1[i];
    __syncthreads();
    int wid = t >> 5, lane = t & 31;
    float* xs = xsb + wid * 512;
    int warps = gridDim.x * 16;
    const float inv_sc = 0.0625f;      // 1/sqrt(64*4)
    const float4* w0 = (const float4*)wsc0;
    const float2* w1 = (const float2*)wsc1;

    for (int nb = (blockIdx.x * 16 + wid) * 2; nb < Nn; nb += warps * 2) {
        __syncwarp();
        #pragma unroll
        for (int nn = 0; nn < 2; nn++) {
            int n = nb + nn;
            if (n < Nn) {
                const float4* src = (const float4*)(nf + (size_t)n * 256);
                float4* dst = (float4*)(xs + nn * 256);
                dst[lane] = src[lane];
                dst[lane + 32] = src[lane + 32];
            }
        }
        float naz[2][4];
        #pragma unroll
        for (int nn = 0; nn < 2; nn++) {
            int n = (nb + nn < Nn) ? nb + nn : 0;
            float4 v = *(const float4*)(na + (size_t)n * 4);
            naz[nn][0] = v.x; naz[nn][1] = v.y; naz[nn][2] = v.z; naz[nn][3] = v.w;
        }
        __syncwarp();

        float4 acc0[2];
        #pragma unroll
        for (int nn = 0; nn < 2; nn++) acc0[nn] = make_float4(0, 0, 0, 0);
        #pragma unroll 4
        for (int u = 0; u < 64; u++) {
            float xv0 = xs[u], xv1 = xs[256 + u];
            #pragma unroll
            for (int z = 0; z < 4; z++) {
                float4 wv = w0[(u * 4 + z) * 32 + lane];
                float y0 = xv0 * naz[0][z];
                float y1 = xv1 * naz[1][z];
                acc0[0].x += y0 * wv.x; acc0[0].y += y0 * wv.y;
                acc0[0].z += y0 * wv.z; acc0[0].w += y0 * wv.w;
                acc0[1].x += y1 * wv.x; acc0[1].y += y1 * wv.y;
                acc0[1].z += y1 * wv.z; acc0[1].w += y1 * wv.w;
            }
        }

        float a1[2][2][3];
        #pragma unroll
        for (int nn = 0; nn < 2; nn++)
            #pragma unroll
            for (int p = 0; p < 2; p++)
                #pragma unroll
                for (int d = 0; d < 3; d++) a1[nn][p][d] = 0.f;
        #pragma unroll 4
        for (int u = 0; u < 64; u++) {
            float2 wz0 = w1[(u * 4 + 0) * 32 + lane];
            float2 wz1 = w1[(u * 4 + 1) * 32 + lane];
            float2 wz2 = w1[(u * 4 + 2) * 32 + lane];
            float2 wz3 = w1[(u * 4 + 3) * 32 + lane];
            #pragma unroll
            for (int nn = 0; nn < 2; nn++) {
                float wrx = naz[nn][0] * wz0.x + naz[nn][1] * wz1.x
                          + naz[nn][2] * wz2.x + naz[nn][3] * wz3.x;
                float wry = naz[nn][0] * wz0.y + naz[nn][1] * wz1.y
                          + naz[nn][2] * wz2.y + naz[nn][3] * wz3.y;
                float gx = xs[nn * 256 + 64 + u * 3];
                float gy = xs[nn * 256 + 64 + u * 3 + 1];
                float gz = xs[nn * 256 + 64 + u * 3 + 2];
                a1[nn][0][0] += wrx * gx; a1[nn][0][1] += wrx * gy; a1[nn][0][2] += wrx * gz;
                a1[nn][1][0] += wry * gx; a1[nn][1][1] += wry * gy; a1[nn][1][2] += wry * gz;
            }
        }

        #pragma unroll
        for (int nn = 0; nn < 2; nn++) {
            int n = nb + nn;
            if (n >= Nn) continue;
            float4 r0;
            r0.x = acc0[nn].x * inv_sc; r0.y = acc0[nn].y * inv_sc;
            r0.z = acc0[nn].z * inv_sc; r0.w = acc0[nn].w * inv_sc;
            ((float4*)(g_sc + (size_t)n * 320))[lane] = r0;
            float* o = g_sc + (size_t)n * 320 + 128 + lane * 6;
            o[0] = a1[nn][0][0] * inv_sc; o[1] = a1[nn][0][1] * inv_sc;
            o[2] = a1[nn][0][2] * inv_sc; o[3] = a1[nn][1][0] * inv_sc;
            o[4] = a1[nn][1][1] * inv_sc; o[5] = a1[nn][1][2] * inv_sc;
        }
    }
}

// ---------------- fused gather-reduce + lin2 + skip + gate + output ----------------
// round-10 proven config (141us): 512 thr, Wm2 in registers, 3-stride s1 staging
__global__ __launch_bounds__(512, 1)
void k_final(const float* __restrict__ nf,
             const float* __restrict__ Wm2, const float* __restrict__ Wl20,
             const float* __restrict__ Wl21, float* __restrict__ out) {
    float* wl20 = smem_dyn;          // 16384 floats
    float* wl21 = wl20 + 16384;      // 8192
    float* stg  = wl21 + 8192;       // 16 warps * 2 nodes * 512
    int t = threadIdx.x;             // 512
    for (int i = t; i < 16384; i += 512) wl20[i] = Wl20[i];
    for (int i = t; i < 8192; i += 512) wl21[i] = Wl21[i];
    __syncthreads();

    int wid = t >> 5, lane = t & 31;
    float* stw = stg + wid * 1024;   // 2 nodes * 512
    const float inv_e = 0.35355339059327373f;   // 1/sqrt(8)
    const float inv_n = 0.35355339059327373f;   // 1/sqrt(8)
    const float inv2  = 0.08838834764831845f;   // 1/sqrt(128)
    const float is3   = 0.5773502691896258f;    // 1/sqrt(3)
    int warps = gridDim.x * 16;

    float4 wr[2][8];
    #pragma unroll
    for (int p = 0; p < 2; p++) {
        int u = lane + p * 32;
        #pragma unroll
        for (int j = 0; j < 8; j++) {
            wr[p][j].x = Wm2[j * 256 + u];
            wr[p][j].y = Wm2[j * 256 + 64 + u];
            wr[p][j].z = Wm2[j * 256 + 128 + u];
            wr[p][j].w = Wm2[j * 256 + 192 + u];
        }
    }

    const float4* hid4 = (const float4*)g_hid;
    const float4* eap4 = (const float4*)g_eap;

    for (int nb = (blockIdx.x * 16 + wid) * 2; nb < Nn; nb += warps * 2) {
        __syncwarp();
        #pragma unroll 1
        for (int nn = 0; nn < 2; nn++) {
            int n = nb + nn;
            int beg = (n < Nn) ? g_off[n] : 0;
            int end = (n < Nn) ? g_off[n + 1] : 0;
            float s0a[2] = {0, 0}, s0b[2] = {0, 0};
            float s1a[2][3] = {{0, 0, 0}, {0, 0, 0}};
            float s1b[2][3] = {{0, 0, 0}, {0, 0, 0}};

            float4 hv0_n = {0,0,0,0}, hv1_n = {0,0,0,0}, ea_n = {0,0,0,0};
            float4 ha_n = {0,0,0,0}, hb_n = {0,0,0,0};
            if (beg < end) {
                int s0 = g_esrc[beg];           // already *64 (float4 rows)
                hv0_n = hid4[(size_t)beg * 2]; hv1_n = hid4[(size_t)beg * 2 + 1];
                ea_n  = eap4[beg];
                const float4* hp = (const float4*)g_h + s0;
                ha_n = hp[lane]; hb_n = hp[lane + 32];
            }
            for (int i = beg; i < end; i++) {
                float4 hv0 = hv0_n, hv1 = hv1_n, eav = ea_n, ha = ha_n, hb = hb_n;
                if (i + 1 < end) {
                    int s1 = g_esrc[i + 1];
                    hv0_n = hid4[(size_t)(i + 1) * 2]; hv1_n = hid4[(size_t)(i + 1) * 2 + 1];
                    ea_n  = eap4[i + 1];
                    const float4* hp = (const float4*)g_h + s1;
                    ha_n = hp[lane]; hb_n = hp[lane + 32];
                }
                float hid[8] = { hv0.x, hv0.y, hv0.z, hv0.w, hv1.x, hv1.y, hv1.z, hv1.w };
                #pragma unroll
                for (int p = 0; p < 2; p++) {
                    float4 hvv = (p == 0) ? ha : hb;
                    float w1 = 0, w2 = 0, w3 = 0, w4 = 0;
                    #pragma unroll
                    for (int j = 0; j < 8; j++) {
                        float h = hid[j];
                        w1 += h * wr[p][j].x; w2 += h * wr[p][j].y;
                        w3 += h * wr[p][j].z; w4 += h * wr[p][j].w;
                    }
                    w1 *= inv_e; w2 *= inv_e; w3 *= inv_e; w4 *= inv_e;
                    float g0 = hvv.x, gx = hvv.y, gy = hvv.z, gz = hvv.w;
                    s0a[p] += w1 * g0 * eav.x;
                    s0b[p] += w4 * (gx * eav.y + gy * eav.z + gz * eav.w) * is3;
                    float c = w2 * g0;
                    s1a[p][0] += c * eav.y; s1a[p][1] += c * eav.z; s1a[p][2] += c * eav.w;
                    float b = w3 * eav.x;
                    s1b[p][0] += b * gx; s1b[p][1] += b * gy; s1b[p][2] += b * gz;
                }
            }
            float* st = stw + nn * 512;
            #pragma unroll
            for (int p = 0; p < 2; p++) {
                int u = lane + p * 32;
                st[u]      = s0a[p] * inv_n;
                st[64 + u] = s0b[p] * inv_n;
                #pragma unroll
                for (int d = 0; d < 3; d++) {
                    st[128 + u * 3 + d]        = s1a[p][d] * inv_n;
                    st[128 + (64 + u) * 3 + d] = s1b[p][d] * inv_n;
                }
            }
        }
        __syncwarp();

        float4 t0[2];
        #pragma unroll
        for (int nn = 0; nn < 2; nn++) t0[nn] = make_float4(0, 0, 0, 0);
        const float4* wp = (const float4*)wl20;
        #pragma unroll 4
        for (int k = 0; k < 128; k++) {
            float4 wv = wp[k * 32 + lane];
            #pragma unroll
            for (int nn = 0; nn < 2; nn++) {
                float s = stw[nn * 512 + k];
                t0[nn].x += s * wv.x; t0[nn].y += s * wv.y;
                t0[nn].z += s * wv.z; t0[nn].w += s * wv.w;
            }
        }
        float t1[2][2][3];
        #pragma unroll
        for (int nn = 0; nn < 2; nn++)
            #pragma unroll
            for (int p = 0; p < 2; p++)
                #pragma unroll
                for (int d = 0; d < 3; d++) t1[nn][p][d] = 0.f;
        const float2* wq = (const float2*)wl21;
        #pragma unroll 4
        for (int k = 0; k < 128; k++) {
            float2 wv = wq[k * 32 + lane];
            #pragma unroll
            for (int nn = 0; nn < 2; nn++) {
                const float* sb = stw + nn * 512 + 128 + k * 3;
                float y0 = sb[0], y1 = sb[1], y2 = sb[2];
                t1[nn][0][0] += wv.x * y0; t1[nn][0][1] += wv.x * y1; t1[nn][0][2] += wv.x * y2;
                t1[nn][1][0] += wv.y * y0; t1[nn][1][1] += wv.y * y1; t1[nn][1][2] += wv.y * y2;
            }
        }
        __syncwarp();

        #pragma unroll 1
        for (int nn = 0; nn < 2; nn++) {
            int n = nb + nn;
            if (n >= Nn) continue;
            float* st = stw + nn * 512;
            float4 sc0 = ((const float4*)(g_sc + (size_t)n * 320))[lane];
            float4 tt;
            tt.x = t0[nn].x * inv2 + sc0.x; tt.y = t0[nn].y * inv2 + sc0.y;
            tt.z = t0[nn].z * inv2 + sc0.z; tt.w = t0[nn].w * inv2 + sc0.w;
            int wbase = lane * 4;
            if (wbase < 64) {
                float4 nfv = ((const float4*)(nf + (size_t)n * 256))[lane];
                float4 ov;
                ov.x = nfv.x + silu_f(tt.x); ov.y = nfv.y + silu_f(tt.y);
                ov.z = nfv.z + silu_f(tt.z); ov.w = nfv.w + silu_f(tt.w);
                ((float4*)(out + (size_t)n * 256))[lane] = ov;
            } else {
                int u = wbase - 64;
                st[u]     = silu_f(tt.x);
                st[u + 1] = silu_f(tt.y);
                st[u + 2] = silu_f(tt.z);
                st[u + 3] = silu_f(tt.w);
            }
            __syncwarp();
            int w = lane * 2;
            const float* sc1 = g_sc + (size_t)n * 320 + 128;
            float gate0 = st[w], gate1 = st[w + 1];
            float* ob = out + (size_t)n * 256;
            const float* nb2 = nf + (size_t)n * 256;
            #pragma unroll
            for (int d = 0; d < 3; d++) {
                int c0 = 64 + w * 3 + d, c1 = 64 + (w + 1) * 3 + d;
                ob[c0] = nb2[c0] + gate0 * (t1[nn][0][d] * inv2 + sc1[w * 3 + d]);
                ob[c1] = nb2[c1] + gate1 * (t1[nn][1][d] * inv2 + sc1[(w + 1) * 3 + d]);
            }
            __syncwarp();
        }
    }
}

// ---------------- host ----------------
extern "C" void kernel_launch(void* const* d_in, const int* in_sizes, int n_in,
                              void* d_out, int out_size) {
    const float* nf   = (const float*)d_in[0];
    const float* na   = (const float*)d_in[1];
    const float* ea   = (const float*)d_in[2];
    const float* emb  = (const float*)d_in[3];
    const float* W10  = (const float*)d_in[4];
    const float* W11  = (const float*)d_in[5];
    const float* Wm1  = (const float*)d_in[6];
    const float* Wm2  = (const float*)d_in[7];
    const float* Wl20 = (const float*)d_in[8];
    const float* Wl21 = (const float*)d_in[9];
    const float* Wsc0 = (const float*)d_in[10];
    const float* Wsc1 = (const float*)d_in[11];
    const int*   ei   = (const int*)d_in[12];
    float* out = (float*)d_out;

    cudaFuncSetAttribute(k_sc,    cudaFuncAttributeMaxDynamicSharedMemorySize, 229376);
    cudaFuncSetAttribute(k_final, cudaFuncAttributeMaxDynamicSharedMemorySize, 163840);

    // lazy side-stream + events for fork/join (created once; no device memory)
    static cudaStream_t s2 = nullptr;
    static cudaEvent_t evFork = nullptr, evJoin = nullptr;
    if (s2 == nullptr) {
        cudaStreamCreateWithFlags(&s2, cudaStreamNonBlocking);
        cudaEventCreateWithFlags(&evFork, cudaEventDisableTiming);
        cudaEventCreateWithFlags(&evJoin, cudaEventDisableTiming);
    }

    // fork: k_h runs on s2 concurrently with cooperative k_csr on the main stream
    cudaEventRecord(evFork, 0);
    cudaStreamWaitEvent(s2, evFork, 0);
    k_h<<<1024, 256, 0, s2>>>(nf, W10, W11);
    cudaEventRecord(evJoin, s2);

    // cooperative CSR + edge prep on main stream (overlaps k_h)
    void* csr_args[] = { (void*)&ei, (void*)&emb, (void*)&ea, (void*)&Wm1 };
    cudaLaunchCooperativeKernel((void*)k_csr, dim3(CSR_BLOCKS), dim3(512), csr_args, 0, 0);

    // join: k_sc must wait for k_h (k_final needs g_h written; k_sc orders after join)
    cudaStreamWaitEvent(0, evJoin, 0);

    k_sc<<<148, 512, 229376>>>(nf, na, Wsc0, Wsc1);
    k_final<<<148, 512, 163840>>>(nf, Wm2, Wl20, Wl21, out);
}

// round 16
// speedup vs baseline: 1.0932x; 1.0932x over previous
#include <cuda_runtime.h>
#include <cooperative_groups.h>
namespace cg = cooperative_groups;

#define Nn 20000
#define Ee 160000

// ---------------- scratch (device globals: allocation-free) ----------------
__device__ float g_h[Nn * 256];      // per node: [u][ h0, h1x, h1y, h1z ] interleaved
__device__ float g_sc[Nn * 320];     // [sc0(128) | sc1 as w*3+d (192)]
__device__ int   g_cnt[Nn];
__device__ int   g_cur[Nn];
__device__ int   g_off[Nn + 1];
__device__ int   g_bsum[256];
__device__ int   g_esrc[Ee];         // src*64 (float4 row index into g_h) per dst-sorted edge
__device__ float g_hid[Ee * 8];      // silu(emb@Wm1) per dst-sorted edge
__device__ float g_eap[Ee * 4];      // edge_attrs per dst-sorted edge

__device__ __forceinline__ float silu_f(float x) { return x / (1.0f + __expf(-x)); }

extern __shared__ float smem_dyn[];

// ---------------- CSR build + fused edge prep: cooperative, parallel scan ----------
#define CSR_BLOCKS 148
#define CSR_CHUNK  ((Nn + CSR_BLOCKS - 1) / CSR_BLOCKS)   // 136

__global__ void k_csr(const int* __restrict__ ei, const float* __restrict__ emb,
                      const float* __restrict__ ea, const float* __restrict__ Wm1) {
    cg::grid_group grid = cg::this_grid();
    __shared__ float wm1[64];
    __shared__ int sh[512];
    int t = threadIdx.x;
    int tid = blockIdx.x * blockDim.x + t;
    int nthr = gridDim.x * blockDim.x;
    if (t < 64) wm1[t] = Wm1[t];
    __syncthreads();

    for (int i = tid; i < Nn; i += nthr) { g_cnt[i] = 0; g_cur[i] = 0; }
    grid.sync();

    for (int e = tid; e < Ee; e += nthr) atomicAdd(&g_cnt[ei[Ee + e]], 1);
    grid.sync();

    int base = blockIdx.x * CSR_CHUNK;
    {
        int v = (t < CSR_CHUNK && base + t < Nn) ? g_cnt[base + t] : 0;
        sh[t] = v;
        __syncthreads();
        for (int off = 1; off < 512; off <<= 1) {
            int x = (t >= off) ? sh[t - off] : 0;
            __syncthreads();
            sh[t] += x;
            __syncthreads();
        }
        if (t < CSR_CHUNK && base + t < Nn) g_off[base + t] = sh[t] - v;  // local excl
        if (t == 511) g_bsum[blockIdx.x] = sh[511];
        __syncthreads();
    }
    grid.sync();

    if (blockIdx.x == 0) {
        int v = (t < CSR_BLOCKS) ? g_bsum[t] : 0;
        sh[t] = v;
        __syncthreads();
        for (int off = 1; off < 512; off <<= 1) {
            int x = (t >= off) ? sh[t - off] : 0;
            __syncthreads();
            sh[t] += x;
            __syncthreads();
        }
        if (t < CSR_BLOCKS) g_bsum[t] = sh[t] - v;  // exclusive
        if (t == CSR_BLOCKS - 1) g_off[Nn] = sh[t];
    }
    grid.sync();

    {
        int pre = g_bsum[blockIdx.x];
        if (t < CSR_CHUNK && base + t < Nn) g_off[base + t] += pre;
    }
    grid.sync();

    const float inv_e = 0.35355339059327373f;   // 1/sqrt(8)
    for (int e = tid; e < Ee; e += nthr) {
        int src = ei[e];
        int dst = ei[Ee + e];
        int pos = g_off[dst] + atomicAdd(&g_cur[dst], 1);
        g_esrc[pos] = src * 64;     // pre-scaled float4-row index
        float4 e0 = *(const float4*)(emb + (size_t)e * 8);
        float4 e1 = *(const float4*)(emb + (size_t)e * 8 + 4);
        float h[8];
        #pragma unroll
        for (int j = 0; j < 8; j++) {
            float a = e0.x * wm1[0 * 8 + j] + e0.y * wm1[1 * 8 + j]
                    + e0.z * wm1[2 * 8 + j] + e0.w * wm1[3 * 8 + j]
                    + e1.x * wm1[4 * 8 + j] + e1.y * wm1[5 * 8 + j]
                    + e1.z * wm1[6 * 8 + j] + e1.w * wm1[7 * 8 + j];
            h[j] = silu_f(a * inv_e);
        }
        *(float4*)(g_hid + (size_t)pos * 8)     = make_float4(h[0], h[1], h[2], h[3]);
        *(float4*)(g_hid + (size_t)pos * 8 + 4) = make_float4(h[4], h[5], h[6], h[7]);
        *(float4*)(g_eap + (size_t)pos * 4) = *(const float4*)(ea + (size_t)e * 4);
    }
}

// ---------------- h = lin1(node_feats), interleaved output layout ----------------
__global__ void k_h(const float* __restrict__ nf,
                    const float* __restrict__ W10, const float* __restrict__ W11) {
    __shared__ float w10[4096], w11[4096], xs[256], os[256];
    int t = threadIdx.x;
    for (int i = t; i < 4096; i += 256) { w10[i] = W10[i]; w11[i] = W11[i]; }
    __syncthreads();
    for (int n = blockIdx.x; n < Nn; n += gridDim.x) {
        xs[t] = nf[(size_t)n * 256 + t];
        __syncthreads();
        float acc = 0.f;
        if (t < 64) {
            #pragma unroll 8
            for (int k = 0; k < 64; k++) acc += xs[k] * w10[k * 64 + t];
            os[t * 4] = acc * 0.125f;
        } else {
            int i = t - 64, d = i >> 6, v = i & 63;
            #pragma unroll 8
            for (int k = 0; k < 64; k++) acc += xs[64 + k * 3 + d] * w11[k * 64 + v];
            os[v * 4 + 1 + d] = acc * 0.125f;
        }
        __syncthreads();
        g_h[(size_t)n * 256 + t] = os[t];
        __syncthreads();
    }
}

// ---------------- sc0: weights-only smem (128KB), x0 in registers via shfl ----------
__global__ __launch_bounds__(512, 2)
void k_sc0(const float* __restrict__ nf, const float* __restrict__ na,
           const float* __restrict__ Wsc0) {
    float* wsc0 = smem_dyn;            // 32768 floats (128KB)
    int t = threadIdx.x;               // 512 threads
    for (int i = t; i < 32768; i += 512) wsc0[i] = Wsc0[i];
    __syncthreads();
    int wid = t >> 5, lane = t & 31;
    int warps = gridDim.x * 16;
    const float inv_sc = 0.0625f;      // 1/sqrt(64*4)
    const float4* w0 = (const float4*)wsc0;

    for (int nb = (blockIdx.x * 16 + wid) * 2; nb < Nn; nb += warps * 2) {
        // x0 in registers: lane holds x0[2*lane], x0[2*lane+1] per node
        float2 xr[2];
        float naz[2][4];
        #pragma unroll
        for (int nn = 0; nn < 2; nn++) {
            int n = (nb + nn < Nn) ? nb + nn : Nn - 1;
            xr[nn] = ((const float2*)(nf + (size_t)n * 256))[lane];
            float4 v = *(const float4*)(na + (size_t)n * 4);
            naz[nn][0] = v.x; naz[nn][1] = v.y; naz[nn][2] = v.z; naz[nn][3] = v.w;
        }
        float4 acc0[2];
        acc0[0] = make_float4(0, 0, 0, 0);
        acc0[1] = make_float4(0, 0, 0, 0);

        #pragma unroll 2
        for (int uh = 0; uh < 32; uh++) {
            // u = 2*uh   -> component .x of lane uh
            float xa0 = __shfl_sync(0xffffffffu, xr[0].x, uh);
            float xa1 = __shfl_sync(0xffffffffu, xr[1].x, uh);
            #pragma unroll
            for (int z = 0; z < 4; z++) {
                float4 wv = w0[((2 * uh) * 4 + z) * 32 + lane];
                float y0 = xa0 * naz[0][z];
                float y1 = xa1 * naz[1][z];
                acc0[0].x += y0 * wv.x; acc0[0].y += y0 * wv.y;
                acc0[0].z += y0 * wv.z; acc0[0].w += y0 * wv.w;
                acc0[1].x += y1 * wv.x; acc0[1].y += y1 * wv.y;
                acc0[1].z += y1 * wv.z; acc0[1].w += y1 * wv.w;
            }
            // u = 2*uh+1 -> component .y of lane uh
            float xb0 = __shfl_sync(0xffffffffu, xr[0].y, uh);
            float xb1 = __shfl_sync(0xffffffffu, xr[1].y, uh);
            #pragma unroll
            for (int z = 0; z < 4; z++) {
                float4 wv = w0[((2 * uh + 1) * 4 + z) * 32 + lane];
                float y0 = xb0 * naz[0][z];
                float y1 = xb1 * naz[1][z];
                acc0[0].x += y0 * wv.x; acc0[0].y += y0 * wv.y;
                acc0[0].z += y0 * wv.z; acc0[0].w += y0 * wv.w;
                acc0[1].x += y1 * wv.x; acc0[1].y += y1 * wv.y;
                acc0[1].z += y1 * wv.z; acc0[1].w += y1 * wv.w;
            }
        }

        #pragma unroll
        for (int nn = 0; nn < 2; nn++) {
            int n = nb + nn;
            if (n >= Nn) continue;
            float4 r0;
            r0.x = acc0[nn].x * inv_sc; r0.y = acc0[nn].y * inv_sc;
            r0.z = acc0[nn].z * inv_sc; r0.w = acc0[nn].w * inv_sc;
            ((float4*)(g_sc + (size_t)n * 320))[lane] = r0;
        }
    }
}

// ---------------- sc1: 64KB weights + 24KB x1 staging ----------------
__global__ __launch_bounds__(512, 2)
void k_sc1(const float* __restrict__ nf, const float* __restrict__ na,
           const float* __restrict__ Wsc1) {
    float* wsc1 = smem_dyn;            // 16384 floats (64KB)
    float* xsb  = wsc1 + 16384;        // 16 warps * 2 nodes * 192 floats (24KB)
    int t = threadIdx.x;               // 512 threads
    for (int i = t; i < 16384; i += 512) wsc1[i] = Wsc1[i];
    __syncthreads();
    int wid = t >> 5, lane = t & 31;
    float* xs = xsb + wid * 384;
    int warps = gridDim.x * 16;
    const float inv_sc = 0.0625f;      // 1/sqrt(64*4)
    const float2* w1 = (const float2*)wsc1;

    for (int nb = (blockIdx.x * 16 + wid) * 2; nb < Nn; nb += warps * 2) {
        __syncwarp();
        #pragma unroll
        for (int nn = 0; nn < 2; nn++) {
            int n = nb + nn;
            if (n < Nn) {
                const float4* src = (const float4*)(nf + (size_t)n * 256 + 64);  // 48 float4
                float4* dst = (float4*)(xs + nn * 192);
                dst[lane] = src[lane];
                if (lane < 16) dst[32 + lane] = src[32 + lane];
            }
        }
        float naz[2][4];
        #pragma unroll
        for (int nn = 0; nn < 2; nn++) {
            int n = (nb + nn < Nn) ? nb + nn : 0;
            float4 v = *(const float4*)(na + (size_t)n * 4);
            naz[nn][0] = v.x; naz[nn][1] = v.y; naz[nn][2] = v.z; naz[nn][3] = v.w;
        }
        __syncwarp();

        float a1[2][2][3];
        #pragma unroll
        for (int nn = 0; nn < 2; nn++)
            #pragma unroll
            for (int p = 0; p < 2; p++)
                #pragma unroll
                for (int d = 0; d < 3; d++) a1[nn][p][d] = 0.f;
        #pragma unroll 4
        for (int u = 0; u < 64; u++) {
            float2 wz0 = w1[(u * 4 + 0) * 32 + lane];
            float2 wz1 = w1[(u * 4 + 1) * 32 + lane];
            float2 wz2 = w1[(u * 4 + 2) * 32 + lane];
            float2 wz3 = w1[(u * 4 + 3) * 32 + lane];
            #pragma unroll
            for (int nn = 0; nn < 2; nn++) {
                float wrx = naz[nn][0] * wz0.x + naz[nn][1] * wz1.x
                          + naz[nn][2] * wz2.x + naz[nn][3] * wz3.x;
                float wry = naz[nn][0] * wz0.y + naz[nn][1] * wz1.y
                          + naz[nn][2] * wz2.y + naz[nn][3] * wz3.y;
                float gx = xs[nn * 192 + u * 3];
                float gy = xs[nn * 192 + u * 3 + 1];
                float gz = xs[nn * 192 + u * 3 + 2];
                a1[nn][0][0] += wrx * gx; a1[nn][0][1] += wrx * gy; a1[nn][0][2] += wrx * gz;
                a1[nn][1][0] += wry * gx; a1[nn][1][1] += wry * gy; a1[nn][1][2] += wry * gz;
            }
        }

        #pragma unroll
        for (int nn = 0; nn < 2; nn++) {
            int n = nb + nn;
            if (n >= Nn) continue;
            float* o = g_sc + (size_t)n * 320 + 128 + lane * 6;
            o[0] = a1[nn][0][0] * inv_sc; o[1] = a1[nn][0][1] * inv_sc;
            o[2] = a1[nn][0][2] * inv_sc; o[3] = a1[nn][1][0] * inv_sc;
            o[4] = a1[nn][1][1] * inv_sc; o[5] = a1[nn][1][2] * inv_sc;
        }
    }
}

// ---------------- fused gather-reduce + lin2 + skip + gate + output ----------------
// round-10 proven config (141us): 512 thr, Wm2 in registers, 3-stride s1 staging
__global__ __launch_bounds__(512, 1)
void k_final(const float* __restrict__ nf,
             const float* __restrict__ Wm2, const float* __restrict__ Wl20,
             const float* __restrict__ Wl21, float* __restrict__ out) {
    float* wl20 = smem_dyn;          // 16384 floats
    float* wl21 = wl20 + 16384;      // 8192
    float* stg  = wl21 + 8192;       // 16 warps * 2 nodes * 512
    int t = threadIdx.x;             // 512
    for (int i = t; i < 16384; i += 512) wl20[i] = Wl20[i];
    for (int i = t; i < 8192; i += 512) wl21[i] = Wl21[i];
    __syncthreads();

    int wid = t >> 5, lane = t & 31;
    float* stw = stg + wid * 1024;   // 2 nodes * 512
    const float inv_e = 0.35355339059327373f;   // 1/sqrt(8)
    const float inv_n = 0.35355339059327373f;   // 1/sqrt(8)
    const float inv2  = 0.08838834764831845f;   // 1/sqrt(128)
    const float is3   = 0.5773502691896258f;    // 1/sqrt(3)
    int warps = gridDim.x * 16;

    float4 wr[2][8];
    #pragma unroll
    for (int p = 0; p < 2; p++) {
        int u = lane + p * 32;
        #pragma unroll
        for (int j = 0; j < 8; j++) {
            wr[p][j].x = Wm2[j * 256 + u];
            wr[p][j].y = Wm2[j * 256 + 64 + u];
            wr[p][j].z = Wm2[j * 256 + 128 + u];
            wr[p][j].w = Wm2[j * 256 + 192 + u];
        }
    }

    const float4* hid4 = (const float4*)g_hid;
    const float4* eap4 = (const float4*)g_eap;

    for (int nb = (blockIdx.x * 16 + wid) * 2; nb < Nn; nb += warps * 2) {
        __syncwarp();
        #pragma unroll 1
        for (int nn = 0; nn < 2; nn++) {
            int n = nb + nn;
            int beg = (n < Nn) ? g_off[n] : 0;
            int end = (n < Nn) ? g_off[n + 1] : 0;
            float s0a[2] = {0, 0}, s0b[2] = {0, 0};
            float s1a[2][3] = {{0, 0, 0}, {0, 0, 0}};
            float s1b[2][3] = {{0, 0, 0}, {0, 0, 0}};

            float4 hv0_n = {0,0,0,0}, hv1_n = {0,0,0,0}, ea_n = {0,0,0,0};
            float4 ha_n = {0,0,0,0}, hb_n = {0,0,0,0};
            if (beg < end) {
                int s0 = g_esrc[beg];           // already *64 (float4 rows)
                hv0_n = hid4[(size_t)beg * 2]; hv1_n = hid4[(size_t)beg * 2 + 1];
                ea_n  = eap4[beg];
                const float4* hp = (const float4*)g_h + s0;
                ha_n = hp[lane]; hb_n = hp[lane + 32];
            }
            for (int i = beg; i < end; i++) {
                float4 hv0 = hv0_n, hv1 = hv1_n, eav = ea_n, ha = ha_n, hb = hb_n;
                if (i + 1 < end) {
                    int s1 = g_esrc[i + 1];
                    hv0_n = hid4[(size_t)(i + 1) * 2]; hv1_n = hid4[(size_t)(i + 1) * 2 + 1];
                    ea_n  = eap4[i + 1];
                    const float4* hp = (const float4*)g_h + s1;
                    ha_n = hp[lane]; hb_n = hp[lane + 32];
                }
                float hid[8] = { hv0.x, hv0.y, hv0.z, hv0.w, hv1.x, hv1.y, hv1.z, hv1.w };
                #pragma unroll
                for (int p = 0; p < 2; p++) {
                    float4 hvv = (p == 0) ? ha : hb;
                    float w1 = 0, w2 = 0, w3 = 0, w4 = 0;
                    #pragma unroll
                    for (int j = 0; j < 8; j++) {
                        float h = hid[j];
                        w1 += h * wr[p][j].x; w2 += h * wr[p][j].y;
                        w3 += h * wr[p][j].z; w4 += h * wr[p][j].w;
                    }
                    w1 *= inv_e; w2 *= inv_e; w3 *= inv_e; w4 *= inv_e;
                    float g0 = hvv.x, gx = hvv.y, gy = hvv.z, gz = hvv.w;
                    s0a[p] += w1 * g0 * eav.x;
                    s0b[p] += w4 * (gx * eav.y + gy * eav.z + gz * eav.w) * is3;
                    float c = w2 * g0;
                    s1a[p][0] += c * eav.y; s1a[p][1] += c * eav.z; s1a[p][2] += c * eav.w;
                    float b = w3 * eav.x;
                    s1b[p][0] += b * gx; s1b[p][1] += b * gy; s1b[p][2] += b * gz;
                }
            }
            float* st = stw + nn * 512;
            #pragma unroll
            for (int p = 0; p < 2; p++) {
                int u = lane + p * 32;
                st[u]      = s0a[p] * inv_n;
                st[64 + u] = s0b[p] * inv_n;
                #pragma unroll
                for (int d = 0; d < 3; d++) {
                    st[128 + u * 3 + d]        = s1a[p][d] * inv_n;
                    st[128 + (64 + u) * 3 + d] = s1b[p][d] * inv_n;
                }
            }
        }
        __syncwarp();

        float4 t0[2];
        #pragma unroll
        for (int nn = 0; nn < 2; nn++) t0[nn] = make_float4(0, 0, 0, 0);
        const float4* wp = (const float4*)wl20;
        #pragma unroll 4
        for (int k = 0; k < 128; k++) {
            float4 wv = wp[k * 32 + lane];
            #pragma unroll
            for (int nn = 0; nn < 2; nn++) {
                float s = stw[nn * 512 + k];
                t0[nn].x += s * wv.x; t0[nn].y += s * wv.y;
                t0[nn].z += s * wv.z; t0[nn].w += s * wv.w;
            }
        }
        float t1[2][2][3];
        #pragma unroll
        for (int nn = 0; nn < 2; nn++)
            #pragma unroll
            for (int p = 0; p < 2; p++)
                #pragma unroll
                for (int d = 0; d < 3; d++) t1[nn][p][d] = 0.f;
        const float2* wq = (const float2*)wl21;
        #pragma unroll 4
        for (int k = 0; k < 128; k++) {
            float2 wv = wq[k * 32 + lane];
            #pragma unroll
            for (int nn = 0; nn < 2; nn++) {
                const float* sb = stw + nn * 512 + 128 + k * 3;
                float y0 = sb[0], y1 = sb[1], y2 = sb[2];
                t1[nn][0][0] += wv.x * y0; t1[nn][0][1] += wv.x * y1; t1[nn][0][2] += wv.x * y2;
                t1[nn][1][0] += wv.y * y0; t1[nn][1][1] += wv.y * y1; t1[nn][1][2] += wv.y * y2;
            }
        }
        __syncwarp();

        #pragma unroll 1
        for (int nn = 0; nn < 2; nn++) {
            int n = nb + nn;
            if (n >= Nn) continue;
            float* st = stw + nn * 512;
            float4 sc0 = ((const float4*)(g_sc + (size_t)n * 320))[lane];
            float4 tt;
            tt.x = t0[nn].x * inv2 + sc0.x; tt.y = t0[nn].y * inv2 + sc0.y;
            tt.z = t0[nn].z * inv2 + sc0.z; tt.w = t0[nn].w * inv2 + sc0.w;
            int wbase = lane * 4;
            if (wbase < 64) {
                float4 nfv = ((const float4*)(nf + (size_t)n * 256))[lane];
                float4 ov;
                ov.x = nfv.x + silu_f(tt.x); ov.y = nfv.y + silu_f(tt.y);
                ov.z = nfv.z + silu_f(tt.z); ov.w = nfv.w + silu_f(tt.w);
                ((float4*)(out + (size_t)n * 256))[lane] = ov;
            } else {
                int u = wbase - 64;
                st[u]     = silu_f(tt.x);
                st[u + 1] = silu_f(tt.y);
                st[u + 2] = silu_f(tt.z);
                st[u + 3] = silu_f(tt.w);
            }
            __syncwarp();
            int w = lane * 2;
            const float* sc1 = g_sc + (size_t)n * 320 + 128;
            float gate0 = st[w], gate1 = st[w + 1];
            float* ob = out + (size_t)n * 256;
            const float* nb2 = nf + (size_t)n * 256;
            #pragma unroll
            for (int d = 0; d < 3; d++) {
                int c0 = 64 + w * 3 + d, c1 = 64 + (w + 1) * 3 + d;
                ob[c0] = nb2[c0] + gate0 * (t1[nn][0][d] * inv2 + sc1[w * 3 + d]);
                ob[c1] = nb2[c1] + gate1 * (t1[nn][1][d] * inv2 + sc1[(w + 1) * 3 + d]);
            }
            __syncwarp();
        }
    }
}

// ---------------- host ----------------
extern "C" void kernel_launch(void* const* d_in, const int* in_sizes, int n_in,
                              void* d_out, int out_size) {
    const float* nf   = (const float*)d_in[0];
    const float* na   = (const float*)d_in[1];
    const float* ea   = (const float*)d_in[2];
    const float* emb  = (const float*)d_in[3];
    const float* W10  = (const float*)d_in[4];
    const float* W11  = (const float*)d_in[5];
    const float* Wm1  = (const float*)d_in[6];
    const float* Wm2  = (const float*)d_in[7];
    const float* Wl20 = (const float*)d_in[8];
    const float* Wl21 = (const float*)d_in[9];
    const float* Wsc0 = (const float*)d_in[10];
    const float* Wsc1 = (const float*)d_in[11];
    const int*   ei   = (const int*)d_in[12];
    float* out = (float*)d_out;

    cudaFuncSetAttribute(k_sc0,   cudaFuncAttributeMaxDynamicSharedMemorySize, 131072);
    cudaFuncSetAttribute(k_sc1,   cudaFuncAttributeMaxDynamicSharedMemorySize, 90112);
    cudaFuncSetAttribute(k_final, cudaFuncAttributeMaxDynamicSharedMemorySize, 163840);

    // lazy side-stream + events (created once; no device memory)
    static cudaStream_t s2 = nullptr;
    static cudaEvent_t evFork = nullptr, evJoin = nullptr;
    if (s2 == nullptr) {
        cudaStreamCreateWithFlags(&s2, cudaStreamNonBlocking);
        cudaEventCreateWithFlags(&evFork, cudaEventDisableTiming);
        cudaEventCreateWithFlags(&evJoin, cudaEventDisableTiming);
    }

    // launch #1: CSR + edge prep (cooperative; nothing overlaps it)
    void* csr_args[] = { (void*)&ei, (void*)&emb, (void*)&ea, (void*)&Wm1 };
    cudaLaunchCooperativeKernel((void*)k_csr, dim3(CSR_BLOCKS), dim3(512), csr_args, 0, 0);

    // fork after k_csr: side stream runs k_sc1 concurrently with k_h + k_sc0
    cudaEventRecord(evFork, 0);
    cudaStreamWaitEvent(s2, evFork, 0);
    k_sc1<<<148, 512, 90112, s2>>>(nf, na, Wsc1);          // launch #2 (s2)
    cudaEventRecord(evJoin, s2);

    k_h<<<1024, 256>>>(nf, W10, W11);                       // launch #3 (main)
    k_sc0<<<148, 512, 131072>>>(nf, na, Wsc0);              // launch #4 (main, capture)

    // join: k_final needs g_sc halves from both streams
    cudaStreamWaitEvent(0, evJoin, 0);
    k_final<<<148, 512, 163840>>>(nf, Wm2, Wl20, Wl21, out);
}